// round 7
// baseline (speedup 1.0000x reference)
#include <cuda_runtime.h>
#include <math.h>

#define IMG 256
#define MAX_R 64
#define N_AG 2047
#define N_OB 2048
#define N_ENT 4095
#define FOVH 0.7853981633974483f   /* pi/4 = FOV/2 */
#define PT 1024

#define NSTRIPE 32
#define SSHIFT 3                   /* 8 columns per stripe */
#define CAP 4096                   /* per-stripe capacity (>= N_ENT, safe) */

/* stripe bins: {pxi<<16 | pr*pr, depth_bits} */
__device__ uint2 g_bin[NSTRIPE * CAP];
__device__ int   g_cnt[NSTRIPE];    /* zero-init at load; self-reset each run */
__device__ int   g_done[NSTRIPE];   /* zero-init at load; self-reset each run */

__global__ void transform_kernel(const float* __restrict__ agent,
                                 const float* __restrict__ goal,
                                 const float* __restrict__ others,
                                 const float* __restrict__ obs) {
    int e = blockIdx.x * blockDim.x + threadIdx.x;
    if (e >= N_ENT) return;

    float ax = agent[0], ay = agent[1];
    float vx = goal[0] - ax, vy = goal[1] - ay;
    float inv = 1.0f / (sqrtf(vx * vx + vy * vy) + 1e-8f);
    vx *= inv; vy *= inv;
    float c = vy, s = vx;

    float ex, ey, r, h;
    if (e < N_AG) {
        ex = others[2 * e];
        ey = others[2 * e + 1];
        r  = 0.05f;
        h  = 0.2f;
    } else {
        int o = e - N_AG;
        ex = obs[3 * o];
        ey = obs[3 * o + 1];
        r  = obs[3 * o + 2];
        h  = 0.5f;
    }

    float rx = ex - ax, ry = ey - ay;
    float camx =  c * rx + s * ry;
    float camy = -s * rx + c * ry;
    float dist = sqrtf(camx * camx + camy * camy);
    float angle = atan2f(camx, camy);

    if (!((camy >= 0.0f) && (dist <= 3.0f) && (fabsf(angle) <= FOVH)))
        return;

    float pixel_x = angle / FOVH * 0.5f;
    int pxi = (int)floorf((pixel_x + 0.5f) * (float)IMG);
    int pr  = (int)floorf(r / (dist + 1e-8f) * (float)IMG * 0.5f);
    pr = min(max(pr, 1), MAX_R);
    float depth = fminf(dist / 3.0f, 1.0f) * (1.0f - h * 0.3f);
    depth = fmaxf(depth, 0.0f);

    int lo = pxi - pr, hi = pxi + pr;
    if (hi < 0 || lo >= IMG) return;
    lo = max(lo, 0); hi = min(hi, IMG - 1);

    uint2 rec = make_uint2(((unsigned)pxi << 16) | (unsigned)(pr * pr),
                           __float_as_uint(depth));
    int s1 = hi >> SSHIFT;
    for (int st = lo >> SSHIFT; st <= s1; st++) {
        int idx = atomicAdd(&g_cnt[st], 1);
        g_bin[st * CAP + idx] = rec;
    }
}

__global__ __launch_bounds__(PT)
void paint_kernel(float* __restrict__ out) {
    __shared__ uint2 s_rec[CAP];       /* {rem = pr2-dx2, depth_bits} */
    __shared__ int   s_wcnt[32];
    __shared__ int   s_wbase[33];
    __shared__ float s_min[PT];

    int tid  = threadIdx.x;
    int col  = blockIdx.x;
    int st   = col >> SSHIFT;
    int warp = tid >> 5;
    unsigned lane = tid & 31;

    int n = g_cnt[st];
    const uint2* __restrict__ bin = g_bin + st * CAP;

    /* Phase A: load stripe bin, test this column, compute per-warp counts.
       n is normally << PT so only k=0 does real loads. */
    uint2 r[4]; int rem[4]; unsigned msk[4]; int cnt = 0;
    #pragma unroll
    for (int k = 0; k < 4; k++) {
        int e = tid + k * PT;
        bool inr = (e < n);
        uint2 g = inr ? __ldg(&bin[e]) : make_uint2(0u, 0u);
        int pxi = (int)g.x >> 16;
        int pr2 = (int)(g.x & 0xffffu);
        int dx  = col - pxi;
        rem[k]  = inr ? (pr2 - dx * dx) : -1;
        r[k]    = g;
        msk[k]  = __ballot_sync(0xffffffffu, rem[k] >= 0);
        cnt    += __popc(msk[k]);
    }
    if (lane == 0) s_wcnt[warp] = cnt;
    __syncthreads();

    if (warp == 0) {                    /* exclusive scan of 32 warp counts */
        int v = s_wcnt[lane];
        int incl = v;
        #pragma unroll
        for (int off = 1; off < 32; off <<= 1) {
            int t = __shfl_up_sync(0xffffffffu, incl, off);
            if ((int)lane >= off) incl += t;
        }
        s_wbase[lane] = incl - v;
        if (lane == 31) s_wbase[32] = incl;
    }
    __syncthreads();

    int base = s_wbase[warp];
    #pragma unroll
    for (int k = 0; k < 4; k++) {
        if (rem[k] >= 0) {
            int pos = base + __popc(msk[k] & ((1u << lane) - 1));
            s_rec[pos] = make_uint2((unsigned)rem[k], r[k].y);
        }
        base += __popc(msk[k]);
    }
    __syncthreads();
    int nc = s_wbase[32];

    /* Self-reset: 8 blocks read this stripe; the 8th arriver (all reads done)
       zeroes the counters for the next graph replay. No waiting involved. */
    if (tid == 0) {
        int d = atomicAdd(&g_done[st], 1);
        if (d == 7) { g_cnt[st] = 0; g_done[st] = 0; }
    }

    /* Phase B: 4 threads per row; rows with dy^2 > MAX_R^2 never hit. */
    int row = tid & 255;
    int q   = tid >> 8;
    int dy  = row - IMG / 2;
    int d2  = dy * dy;
    float mv = 1.0f;
    if (d2 <= MAX_R * MAX_R) {
        #pragma unroll 4
        for (int e = q; e < nc; e += 4) {
            uint2 rr = s_rec[e];
            if (d2 <= (int)rr.x) mv = fminf(mv, __uint_as_float(rr.y));
        }
    }
    s_min[tid] = mv;
    __syncthreads();

    if (tid < 256) {
        float a = fminf(s_min[tid],       s_min[tid + 256]);
        float b = fminf(s_min[tid + 512], s_min[tid + 768]);
        out[tid * IMG + col] = fminf(a, b);
    }
}

extern "C" void kernel_launch(void* const* d_in, const int* in_sizes, int n_in,
                              void* d_out, int out_size) {
    const float* agent  = (const float*)d_in[0];
    const float* goal   = (const float*)d_in[1];
    const float* others = (const float*)d_in[2];
    const float* obs    = (const float*)d_in[3];
    float* out          = (float*)d_out;

    transform_kernel<<<16, 256>>>(agent, goal, others, obs);
    paint_kernel<<<IMG, PT>>>(out);
}

// round 8
// speedup vs baseline: 1.7500x; 1.7500x over previous
#include <cuda_runtime.h>
#include <math.h>

#define IMG 256
#define MAX_R 64
#define N_AG 2047
#define N_OB 2048
#define N_ENT 4095
#define FOVH 0.7853981633974483f   /* pi/4 = FOV/2 */
#define PT 1024

/* dense valid records: {pxi<<16 | pr*pr, depth_bits} */
__device__ uint2 g_rec[4096];
__device__ int   g_nvalid = 0;     /* self-reset by paint each run */
__device__ int   g_done   = 0;

__global__ void transform_kernel(const float* __restrict__ agent,
                                 const float* __restrict__ goal,
                                 const float* __restrict__ others,
                                 const float* __restrict__ obs) {
    int e = blockIdx.x * blockDim.x + threadIdx.x;
    unsigned lane = threadIdx.x & 31;

    float ax = agent[0], ay = agent[1];
    float vx = goal[0] - ax, vy = goal[1] - ay;
    float inv = 1.0f / (sqrtf(vx * vx + vy * vy) + 1e-8f);
    vx *= inv; vy *= inv;
    float c = vy, s = vx;

    bool valid = false;
    uint2 rec = make_uint2(0u, 0u);

    if (e < N_ENT) {
        float ex, ey, r, h;
        if (e < N_AG) {
            ex = others[2 * e];
            ey = others[2 * e + 1];
            r  = 0.05f;
            h  = 0.2f;
        } else {
            int o = e - N_AG;
            ex = obs[3 * o];
            ey = obs[3 * o + 1];
            r  = obs[3 * o + 2];
            h  = 0.5f;
        }
        float rx = ex - ax, ry = ey - ay;
        float camx =  c * rx + s * ry;
        float camy = -s * rx + c * ry;
        float dist = sqrtf(camx * camx + camy * camy);
        float angle = atan2f(camx, camy);

        if ((camy >= 0.0f) && (dist <= 3.0f) && (fabsf(angle) <= FOVH)) {
            float pixel_x = angle / FOVH * 0.5f;
            int pxi = (int)floorf((pixel_x + 0.5f) * (float)IMG);
            int pr  = (int)floorf(r / (dist + 1e-8f) * (float)IMG * 0.5f);
            pr = min(max(pr, 1), MAX_R);
            if (pxi + pr >= 0 && pxi - pr < IMG) {      /* touches image */
                float depth = fminf(dist / 3.0f, 1.0f) * (1.0f - h * 0.3f);
                depth = fmaxf(depth, 0.0f);
                rec.x = ((unsigned)pxi << 16) | (unsigned)(pr * pr);
                rec.y = __float_as_uint(depth);
                valid = true;
            }
        }
    }

    /* warp-aggregated compaction into dense prefix */
    unsigned m = __ballot_sync(0xffffffffu, valid);
    if (valid) {
        int leader = __ffs(m) - 1;
        int base = 0;
        if ((int)lane == leader) base = atomicAdd(&g_nvalid, __popc(m));
        base = __shfl_sync(m, base, leader);
        g_rec[base + __popc(m & ((1u << lane) - 1))] = rec;
    }
}

__global__ __launch_bounds__(PT)
void paint_kernel(float* __restrict__ out) {
    __shared__ uint2 s_rec[N_ENT];     /* {rem = pr2-dx2, depth_bits} */
    __shared__ int   s_wcnt[32];
    __shared__ int   s_wbase[33];
    __shared__ float s_min[PT];
    __shared__ int   s_n;

    int tid  = threadIdx.x;
    int col  = blockIdx.x;
    int warp = tid >> 5;
    unsigned lane = tid & 31;

    if (tid == 0) s_n = g_nvalid;
    __syncthreads();
    int n = s_n;

    /* self-reset for next graph replay: every block has already captured n
       into smem before the 256th done-arrival can trigger the reset. */
    if (tid == 0) {
        int d = atomicAdd(&g_done, 1);
        if (d == IMG - 1) { g_nvalid = 0; g_done = 0; }
    }

    /* Phase A: hit-test dense records; typically only k=0 is live */
    uint2 r[4]; int rem[4]; unsigned msk[4]; int cnt = 0;
    #pragma unroll
    for (int k = 0; k < 4; k++) {
        int e = tid + k * PT;
        bool inr = (e < n);
        uint2 g = inr ? __ldg(&g_rec[e]) : make_uint2(0u, 0u);
        int pxi = (int)g.x >> 16;
        int pr2 = (int)(g.x & 0xffffu);
        int dx  = col - pxi;
        rem[k]  = inr ? (pr2 - dx * dx) : -1;
        r[k]    = g;
        msk[k]  = __ballot_sync(0xffffffffu, rem[k] >= 0);
        cnt    += __popc(msk[k]);
    }
    if (lane == 0) s_wcnt[warp] = cnt;
    __syncthreads();

    if (warp == 0) {                    /* exclusive scan of 32 warp counts */
        int v = s_wcnt[lane];
        int incl = v;
        #pragma unroll
        for (int off = 1; off < 32; off <<= 1) {
            int t = __shfl_up_sync(0xffffffffu, incl, off);
            if ((int)lane >= off) incl += t;
        }
        s_wbase[lane] = incl - v;
        if (lane == 31) s_wbase[32] = incl;
    }
    __syncthreads();

    int base = s_wbase[warp];
    #pragma unroll
    for (int k = 0; k < 4; k++) {
        if (rem[k] >= 0) {
            int pos = base + __popc(msk[k] & ((1u << lane) - 1));
            s_rec[pos] = make_uint2((unsigned)rem[k], r[k].y);
        }
        base += __popc(msk[k]);
    }
    __syncthreads();
    int nc = s_wbase[32];

    /* Phase B: 4 threads per row; rows with dy^2 > MAX_R^2 never hit */
    int row = tid & 255;
    int q   = tid >> 8;
    int dy  = row - IMG / 2;
    int d2  = dy * dy;
    float mv = 1.0f;
    if (d2 <= MAX_R * MAX_R) {
        #pragma unroll 4
        for (int e = q; e < nc; e += 4) {
            uint2 rr = s_rec[e];
            if (d2 <= (int)rr.x) mv = fminf(mv, __uint_as_float(rr.y));
        }
    }
    s_min[tid] = mv;
    __syncthreads();

    if (tid < 256) {
        float a = fminf(s_min[tid],       s_min[tid + 256]);
        float b = fminf(s_min[tid + 512], s_min[tid + 768]);
        out[tid * IMG + col] = fminf(a, b);
    }
}

extern "C" void kernel_launch(void* const* d_in, const int* in_sizes, int n_in,
                              void* d_out, int out_size) {
    const float* agent  = (const float*)d_in[0];
    const float* goal   = (const float*)d_in[1];
    const float* others = (const float*)d_in[2];
    const float* obs    = (const float*)d_in[3];
    float* out          = (float*)d_out;

    transform_kernel<<<64, 64>>>(agent, goal, others, obs);
    paint_kernel<<<IMG, PT>>>(out);
}